// round 1
// baseline (speedup 1.0000x reference)
#include <cuda_runtime.h>
#include <math.h>

#define NA   32
#define LA   32
#define BB   64
#define LBD  32
#define DIN  768
#define HD   768
#define MQ   (NA*LA)     // 1024
#define MKV  (BB*LBD)    // 2048
#define OT_INV_EPS 10.0f

// ---------------- scratch (device globals; no allocation allowed) ----------
__device__ float g_q[MQ*HD];        // 3 MB
__device__ float g_k[MKV*HD];       // 6 MB
__device__ float g_v[MKV*HD];       // 6 MB
__device__ float g_ecls[NA*HD];
__device__ float g_qinv[MQ];
__device__ float g_kinv[MKV];
__device__ float g_T[MQ*MKV];       // 8 MB  (Q=exp(C/eps) then T in place)

__device__ __forceinline__ float warp_sum(float x) {
#pragma unroll
    for (int o = 16; o > 0; o >>= 1) x += __shfl_xor_sync(0xffffffffu, x, o);
    return x;
}
__device__ __forceinline__ float warp_max(float x) {
#pragma unroll
    for (int o = 16; o > 0; o >>= 1) x = fmaxf(x, __shfl_xor_sync(0xffffffffu, x, o));
    return x;
}

// ---------------- GEMM: C[M,768] = A[M,768] @ W[768,768] + bias ------------
// BM=128, BN=64, BK=16, 256 threads, 8x4 per thread
__global__ void __launch_bounds__(256) gemm_bias_kernel(
    const float* __restrict__ A, const float* __restrict__ W,
    const float* __restrict__ bias, float* __restrict__ C, int M)
{
    constexpr int K = 768, N = 768, BM = 128, BN = 64, BK = 16;
    __shared__ float As[BK][BM];
    __shared__ float Ws[BK][BN];
    const int tid = threadIdx.x;
    const int bm = blockIdx.y * BM;
    const int bn = blockIdx.x * BN;
    const int tr = tid >> 4;    // 0..15
    const int tc = tid & 15;    // 0..15
    float acc[8][4] = {};

    for (int k0 = 0; k0 < K; k0 += BK) {
#pragma unroll
        for (int t = 0; t < 2; t++) {
            int f = tid + t * 256;
            int row = f >> 2;
            int kc = (f & 3) * 4;
            float4 av = make_float4(0.f, 0.f, 0.f, 0.f);
            if (bm + row < M)
                av = *(const float4*)&A[(size_t)(bm + row) * K + k0 + kc];
            As[kc + 0][row] = av.x; As[kc + 1][row] = av.y;
            As[kc + 2][row] = av.z; As[kc + 3][row] = av.w;
        }
        {
            int row = tid >> 4;
            int nc = (tid & 15) * 4;
            *(float4*)&Ws[row][nc] = *(const float4*)&W[(size_t)(k0 + row) * N + bn + nc];
        }
        __syncthreads();
#pragma unroll
        for (int kk = 0; kk < BK; kk++) {
            float a[8], b[4];
            *(float4*)&a[0] = *(float4*)&As[kk][tr * 8];
            *(float4*)&a[4] = *(float4*)&As[kk][tr * 8 + 4];
            *(float4*)&b[0] = *(float4*)&Ws[kk][tc * 4];
#pragma unroll
            for (int ii = 0; ii < 8; ii++)
#pragma unroll
                for (int jj = 0; jj < 4; jj++)
                    acc[ii][jj] = fmaf(a[ii], b[jj], acc[ii][jj]);
        }
        __syncthreads();
    }
    float4 bv = *(const float4*)&bias[bn + tc * 4];
#pragma unroll
    for (int ii = 0; ii < 8; ii++) {
        int m = bm + tr * 8 + ii;
        if (m < M) {
            float4 o;
            o.x = acc[ii][0] + bv.x; o.y = acc[ii][1] + bv.y;
            o.z = acc[ii][2] + bv.z; o.w = acc[ii][3] + bv.w;
            *(float4*)&C[(size_t)m * N + bn + tc * 4] = o;
        }
    }
}

// -------- NT GEMM: Q[1024,2048] = exp( (q@k^T) * qinv[i]*kinv[j] / eps ) ----
__global__ void __launch_bounds__(256) gemm_nt_exp_kernel(
    const float* __restrict__ A, const float* __restrict__ Bk,
    const float* __restrict__ ainv, const float* __restrict__ binv,
    float* __restrict__ C)
{
    constexpr int K = 768, NN = 2048, BM = 128, BN = 64, BK = 16;
    __shared__ float As[BK][BM];
    __shared__ float Bs[BK][BN];
    const int tid = threadIdx.x;
    const int bm = blockIdx.y * BM;
    const int bn = blockIdx.x * BN;
    const int tr = tid >> 4;
    const int tc = tid & 15;
    float acc[8][4] = {};

    for (int k0 = 0; k0 < K; k0 += BK) {
#pragma unroll
        for (int t = 0; t < 2; t++) {
            int f = tid + t * 256;
            int row = f >> 2;
            int kc = (f & 3) * 4;
            float4 av = *(const float4*)&A[(size_t)(bm + row) * K + k0 + kc];
            As[kc + 0][row] = av.x; As[kc + 1][row] = av.y;
            As[kc + 2][row] = av.z; As[kc + 3][row] = av.w;
        }
        {
            int row = tid >> 2;          // 0..63
            int kc = (tid & 3) * 4;
            float4 bv4 = *(const float4*)&Bk[(size_t)(bn + row) * K + k0 + kc];
            Bs[kc + 0][row] = bv4.x; Bs[kc + 1][row] = bv4.y;
            Bs[kc + 2][row] = bv4.z; Bs[kc + 3][row] = bv4.w;
        }
        __syncthreads();
#pragma unroll
        for (int kk = 0; kk < BK; kk++) {
            float a[8], b[4];
            *(float4*)&a[0] = *(float4*)&As[kk][tr * 8];
            *(float4*)&a[4] = *(float4*)&As[kk][tr * 8 + 4];
            *(float4*)&b[0] = *(float4*)&Bs[kk][tc * 4];
#pragma unroll
            for (int ii = 0; ii < 8; ii++)
#pragma unroll
                for (int jj = 0; jj < 4; jj++)
                    acc[ii][jj] = fmaf(a[ii], b[jj], acc[ii][jj]);
        }
        __syncthreads();
    }
#pragma unroll
    for (int ii = 0; ii < 8; ii++) {
        int m = bm + tr * 8 + ii;
        float ai = ainv[m] * OT_INV_EPS;
#pragma unroll
        for (int jj = 0; jj < 4; jj++) {
            int n = bn + tc * 4 + jj;
            float val = acc[ii][jj] * ai * binv[n];
            C[(size_t)m * NN + n] = expf(val);
        }
    }
}

// ---------------- row L2-norm inverse -------------------------------------
__global__ void rownorm_kernel(const float* __restrict__ X, float* __restrict__ inv, int M)
{
    int row = blockIdx.x * 8 + (threadIdx.x >> 5);
    int lane = threadIdx.x & 31;
    if (row >= M) return;
    const float* x = X + (size_t)row * HD;
    float s = 0.f;
#pragma unroll
    for (int p = 0; p < 6; p++) {
        float4 v4 = *(const float4*)&x[lane * 4 + p * 128];
        s += v4.x * v4.x + v4.y * v4.y + v4.z * v4.z + v4.w * v4.w;
    }
    s = warp_sum(s);
    if (lane == 0) inv[row] = 1.0f / fmaxf(sqrtf(s), 1e-8f);
}

// ---------------- Sinkhorn: per (a,b) 32x32 tile ---------------------------
__global__ void __launch_bounds__(1024) sinkhorn_kernel(float* __restrict__ T)
{
    const int a = blockIdx.y, b = blockIdx.x;
    const int i = threadIdx.x >> 5, j = threadIdx.x & 31;
    __shared__ float s[32][33];
    size_t idx = (size_t)(a * 32 + i) * MKV + b * 32 + j;
    float val = T[idx];
#pragma unroll 1
    for (int it = 0; it < 10; it++) {
        float rs = warp_sum(val);        // row sum (warp == row)
        val /= rs;
        s[i][j] = val;
        __syncthreads();
        float cs = 0.f;
#pragma unroll
        for (int r = 0; r < 32; r++) cs += s[r][j];
        val /= cs;
        __syncthreads();
    }
    float n2 = warp_sum(val * val);
    val /= fmaxf(sqrtf(n2), 1e-12f);
    T[idx] = val;
}

// ------------- fused attend + LN1 + softpool + LN2 + scores ----------------
// one CTA per (a,b); 256 threads; dynamic smem
__global__ void __launch_bounds__(256) attend_kernel(
    const float* __restrict__ Tmat, const float* __restrict__ q,
    const float* __restrict__ v, const float* __restrict__ ecls,
    const float* __restrict__ entity_cls, const float* __restrict__ mention_cls,
    const float* __restrict__ ln1_g, const float* __restrict__ ln1_b,
    const float* __restrict__ Wsp, const float* __restrict__ bsp,
    const float* __restrict__ ln2_g, const float* __restrict__ ln2_b,
    float* __restrict__ out)
{
    extern __shared__ float sm[];
    float* sv    = sm;             // 24576
    float* satt  = sv + 24576;     // 24576
    float* sTt   = satt + 24576;   // 32*36 = 1152 (transposed, padded)
    float* sWsp  = sTt + 1152;     // 768
    float* spool = sWsp + 768;     // 768
    float* sS    = spool + 768;    // 32
    float* sW    = sS + 32;        // 32
    float* sred  = sW + 32;        // 64

    const int a = blockIdx.y, b = blockIdx.x;
    const int tid = threadIdx.x, lane = tid & 31, wid = tid >> 5;

    // ---- loads
    const float* vb = v + (size_t)b * 32 * HD;
    for (int t = tid; t < 6144; t += 256)
        *(float4*)&sv[t * 4] = *(const float4*)&vb[t * 4];
    for (int t = tid; t < 1024; t += 256) {
        int i = t >> 5, j = t & 31;
        sTt[j * 36 + i] = Tmat[(size_t)(a * 32 + i) * MKV + b * 32 + j];
    }
    for (int t = tid; t < 768; t += 256) sWsp[t] = Wsp[t];
    __syncthreads();

    // ---- attended = T @ v_b + q_a   (8 rows x float4 per thread-pass)
    {
        const int i0 = (wid & 3) * 8;
        const int dbase0 = (wid >> 2) * 384 + lane * 4;
        const float* qa = q + (size_t)(a * 32) * HD;
#pragma unroll 1
        for (int c = 0; c < 3; c++) {
            const int d = dbase0 + c * 128;
            float4 acc[8];
#pragma unroll
            for (int ii = 0; ii < 8; ii++)
                acc[ii] = *(const float4*)&qa[(i0 + ii) * HD + d];
#pragma unroll 8
            for (int j = 0; j < 32; j++) {
                const float4 vv = *(const float4*)&sv[j * HD + d];
                const float4 t0 = *(const float4*)&sTt[j * 36 + i0];
                const float4 t1 = *(const float4*)&sTt[j * 36 + i0 + 4];
                const float ta[8] = {t0.x, t0.y, t0.z, t0.w, t1.x, t1.y, t1.z, t1.w};
#pragma unroll
                for (int ii = 0; ii < 8; ii++) {
                    acc[ii].x = fmaf(ta[ii], vv.x, acc[ii].x);
                    acc[ii].y = fmaf(ta[ii], vv.y, acc[ii].y);
                    acc[ii].z = fmaf(ta[ii], vv.z, acc[ii].z);
                    acc[ii].w = fmaf(ta[ii], vv.w, acc[ii].w);
                }
            }
#pragma unroll
            for (int ii = 0; ii < 8; ii++)
                *(float4*)&satt[(i0 + ii) * HD + d] = acc[ii];
        }
    }
    __syncthreads();

    // ---- LN1 per row + fused softpool score dot (warp per row, 4 rows/warp)
    const float bsp0 = bsp[0];
#pragma unroll 1
    for (int r = 0; r < 4; r++) {
        const int i = wid + r * 8;
        float* row = &satt[i * HD];
        float s = 0.f, sq = 0.f;
#pragma unroll
        for (int p = 0; p < 6; p++) {
            float4 x = *(float4*)&row[lane * 4 + p * 128];
            s += x.x + x.y + x.z + x.w;
            sq += x.x * x.x + x.y * x.y + x.z * x.z + x.w * x.w;
        }
        s = warp_sum(s); sq = warp_sum(sq);
        const float mean = s * (1.0f / HD);
        const float var = sq * (1.0f / HD) - mean * mean;
        const float rstd = rsqrtf(var + 1e-5f);
        float sc = 0.f;
#pragma unroll
        for (int p = 0; p < 6; p++) {
            const int d = lane * 4 + p * 128;
            float4 x  = *(float4*)&row[d];
            float4 g  = *(const float4*)&ln1_g[d];
            float4 bb = *(const float4*)&ln1_b[d];
            float4 w4 = *(const float4*)&sWsp[d];
            float4 y;
            y.x = (x.x - mean) * rstd * g.x + bb.x;
            y.y = (x.y - mean) * rstd * g.y + bb.y;
            y.z = (x.z - mean) * rstd * g.z + bb.z;
            y.w = (x.w - mean) * rstd * g.w + bb.w;
            *(float4*)&row[d] = y;
            sc += y.x * w4.x + y.y * w4.y + y.z * w4.z + y.w * w4.w;
        }
        sc = warp_sum(sc);
        if (lane == 0) sS[i] = sc + bsp0;
    }
    __syncthreads();

    // ---- softmax over 32 token scores (warp 0)
    if (wid == 0) {
        float sval = sS[lane];
        float mx = warp_max(sval);
        float e = expf(sval - mx);
        float sum = warp_sum(e);
        sW[lane] = e / sum;
    }
    __syncthreads();

    // ---- pooled[d] = sum_i w_i * LN1(att)[i,d]
    for (int d = tid; d < HD; d += 256) {
        float p = 0.f;
#pragma unroll
        for (int i = 0; i < 32; i++) p = fmaf(sW[i], satt[i * HD + d], p);
        spool[d] = p;
    }
    __syncthreads();

    // ---- LN2 over pooled (block reduce)
    float s = 0.f, sq = 0.f;
    for (int d = tid; d < HD; d += 256) {
        float x = spool[d];
        s += x; sq += x * x;
    }
    s = warp_sum(s); sq = warp_sum(sq);
    if (lane == 0) { sred[wid] = s; sred[8 + wid] = sq; }
    __syncthreads();
    if (tid == 0) {
        float ts = 0.f, tq = 0.f;
#pragma unroll
        for (int w = 0; w < 8; w++) { ts += sred[w]; tq += sred[8 + w]; }
        sred[16] = ts; sred[17] = tq;
    }
    __syncthreads();
    const float mean2 = sred[16] * (1.0f / HD);
    const float var2 = sred[17] * (1.0f / HD) - mean2 * mean2;
    const float rstd2 = rsqrtf(var2 + 1e-5f);

    // ---- g2l = ecls_a . LN2(pooled);  g2g = mention_cls_b . entity_cls_a
    const float* ea  = ecls + (size_t)a * HD;
    const float* eca = entity_cls + (size_t)a * HD;
    const float* mcb = mention_cls + (size_t)b * HD;
    float g2l = 0.f, g2g = 0.f;
    for (int d = tid; d < HD; d += 256) {
        float ctx = (spool[d] - mean2) * rstd2 * ln2_g[d] + ln2_b[d];
        g2l = fmaf(ea[d], ctx, g2l);
        g2g = fmaf(eca[d], mcb[d], g2g);
    }
    g2l = warp_sum(g2l); g2g = warp_sum(g2g);
    __syncthreads();   // protect sred reuse
    if (lane == 0) { sred[wid] = g2l; sred[8 + wid] = g2g; }
    __syncthreads();
    if (tid == 0) {
        float tl = 0.f, tg = 0.f;
#pragma unroll
        for (int w = 0; w < 8; w++) { tl += sred[w]; tg += sred[8 + w]; }
        out[b * NA + a] = 0.5f * (tl + tg);
    }
}

// ---------------------------------------------------------------------------
extern "C" void kernel_launch(void* const* d_in, const int* in_sizes, int n_in,
                              void* d_out, int out_size)
{
    const float* entity_cls     = (const float*)d_in[0];
    const float* entity_tokens  = (const float*)d_in[1];
    const float* mention_cls    = (const float*)d_in[2];
    const float* mention_tokens = (const float*)d_in[3];
    const float* Wq   = (const float*)d_in[4];
    const float* bq   = (const float*)d_in[5];
    const float* Wk   = (const float*)d_in[6];
    const float* bk   = (const float*)d_in[7];
    const float* Wv   = (const float*)d_in[8];
    const float* bv   = (const float*)d_in[9];
    const float* ln1g = (const float*)d_in[10];
    const float* ln1b = (const float*)d_in[11];
    const float* Wcls = (const float*)d_in[12];
    const float* bcls = (const float*)d_in[13];
    const float* Wsp  = (const float*)d_in[14];
    const float* bsp  = (const float*)d_in[15];
    const float* ln2g = (const float*)d_in[16];
    const float* ln2b = (const float*)d_in[17];
    float* out = (float*)d_out;

    float *pq, *pk, *pv, *pecls, *pqinv, *pkinv, *pT;
    cudaGetSymbolAddress((void**)&pq,    g_q);
    cudaGetSymbolAddress((void**)&pk,    g_k);
    cudaGetSymbolAddress((void**)&pv,    g_v);
    cudaGetSymbolAddress((void**)&pecls, g_ecls);
    cudaGetSymbolAddress((void**)&pqinv, g_qinv);
    cudaGetSymbolAddress((void**)&pkinv, g_kinv);
    cudaGetSymbolAddress((void**)&pT,    g_T);

    // projections
    gemm_bias_kernel<<<dim3(12, 8),  256>>>(entity_tokens,  Wq,   bq,   pq,    MQ);
    gemm_bias_kernel<<<dim3(12, 16), 256>>>(mention_tokens, Wk,   bk,   pk,    MKV);
    gemm_bias_kernel<<<dim3(12, 16), 256>>>(mention_tokens, Wv,   bv,   pv,    MKV);
    gemm_bias_kernel<<<dim3(12, 1),  256>>>(entity_cls,     Wcls, bcls, pecls, NA);

    // inverse row norms
    rownorm_kernel<<<MQ / 8,  256>>>(pq, pqinv, MQ);
    rownorm_kernel<<<MKV / 8, 256>>>(pk, pkinv, MKV);

    // cosine-sim GEMM fused with exp(C/eps)
    gemm_nt_exp_kernel<<<dim3(32, 8), 256>>>(pq, pk, pqinv, pkinv, pT);

    // Sinkhorn + final L2 row normalize (in place on pT)
    sinkhorn_kernel<<<dim3(BB, NA), 1024>>>(pT);

    // fused attend / LN1 / softpool / LN2 / scores / g2g
    const int smem_bytes = (24576 + 24576 + 1152 + 768 + 768 + 32 + 32 + 64) * 4;
    cudaFuncSetAttribute(attend_kernel, cudaFuncAttributeMaxDynamicSharedMemorySize, smem_bytes);
    attend_kernel<<<dim3(BB, NA), 256, smem_bytes>>>(
        pT, pq, pv, pecls, entity_cls, mention_cls,
        ln1g, ln1b, Wsp, bsp, ln2g, ln2b, out);
}

// round 2
// speedup vs baseline: 1.4144x; 1.4144x over previous
#include <cuda_runtime.h>
#include <math.h>

#define NA   32
#define LA   32
#define BB   64
#define LBD  32
#define DIN  768
#define HD   768
#define MQ   (NA*LA)     // 1024
#define MKV  (BB*LBD)    // 2048
#define OT_INV_EPS 10.0f

typedef unsigned long long u64;

// ---------------- scratch (device globals; no allocation allowed) ----------
__device__ float g_q[MQ*HD];        // 3 MB
__device__ float g_k[MKV*HD];       // 6 MB
__device__ float g_v[MKV*HD];       // 6 MB
__device__ float g_ecls[NA*HD];
__device__ float g_qinv[MQ];
__device__ float g_kinv[MKV];
__device__ float g_T[MQ*MKV];       // 8 MB  exp(C/eps), row-major
__device__ float g_Tp[MQ*MKV];      // 8 MB  sinkhorn output, tile-packed

// ---------------- f32x2 packed-math helpers --------------------------------
__device__ __forceinline__ u64 dup2(float x) {
    u64 r; asm("mov.b64 %0, {%1, %1};" : "=l"(r) : "f"(x)); return r;
}
__device__ __forceinline__ void fma2(u64 &d, u64 a, u64 b) {
    asm("fma.rn.f32x2 %0, %1, %2, %0;" : "+l"(d) : "l"(a), "l"(b));
}
__device__ __forceinline__ float2 unpack2(u64 v) {
    float2 r; asm("mov.b64 {%0, %1}, %2;" : "=f"(r.x), "=f"(r.y) : "l"(v)); return r;
}

__device__ __forceinline__ float warp_sum(float x) {
#pragma unroll
    for (int o = 16; o > 0; o >>= 1) x += __shfl_xor_sync(0xffffffffu, x, o);
    return x;
}
__device__ __forceinline__ float warp_max(float x) {
#pragma unroll
    for (int o = 16; o > 0; o >>= 1) x = fmaxf(x, __shfl_xor_sync(0xffffffffu, x, o));
    return x;
}

// ============================================================================
// Fused projection GEMMs (NN): C[M,768] = A[M,768] @ W[768,768] + bias
// z=0: q   z=1: k   z=2: v   z=3: ecls
// BM=BN=128, BK=8, 256 threads, 8x8 per thread via f32x2
// ============================================================================
__global__ void __launch_bounds__(256) proj_kernel(
    const float* __restrict__ entity_tokens, const float* __restrict__ mention_tokens,
    const float* __restrict__ entity_cls,
    const float* __restrict__ Wq, const float* __restrict__ bq,
    const float* __restrict__ Wk, const float* __restrict__ bk,
    const float* __restrict__ Wv, const float* __restrict__ bv,
    const float* __restrict__ Wcls, const float* __restrict__ bcls)
{
    const float* A; const float* W; const float* bias; float* C; int M;
    switch (blockIdx.z) {
        case 0: if (blockIdx.y >= 8) return;
                A = entity_tokens;  W = Wq;   bias = bq;   C = g_q;    M = MQ;  break;
        case 1: A = mention_tokens; W = Wk;   bias = bk;   C = g_k;    M = MKV; break;
        case 2: A = mention_tokens; W = Wv;   bias = bv;   C = g_v;    M = MKV; break;
        default: if (blockIdx.y >= 1) return;
                A = entity_cls;     W = Wcls; bias = bcls; C = g_ecls; M = NA;  break;
    }
    constexpr int K = 768;
    __shared__ __align__(16) float As[2][8][128];
    __shared__ __align__(16) float Ws[2][8][128];

    const int tid = threadIdx.x;
    const int bm = blockIdx.y * 128;
    const int bn = blockIdx.x * 128;
    const int ar = tid >> 1;            // A row within tile 0..127
    const int ak = (tid & 1) * 4;       // A k within BK: 0 or 4
    const int wr = tid >> 5;            // W row within BK 0..7
    const int wc = (tid & 31) * 4;      // W col 0..124
    const int tr = tid >> 4;            // 0..15
    const int tc = tid & 15;            // 0..15

    float4 av, wv;
    // prologue: load tile 0
    av = (bm + ar < M) ? *(const float4*)&A[(size_t)(bm + ar) * K + ak]
                       : make_float4(0.f, 0.f, 0.f, 0.f);
    wv = *(const float4*)&W[(size_t)wr * K + bn + wc];
    As[0][ak + 0][ar] = av.x; As[0][ak + 1][ar] = av.y;
    As[0][ak + 2][ar] = av.z; As[0][ak + 3][ar] = av.w;
    *(float4*)&Ws[0][wr][wc] = wv;
    __syncthreads();

    u64 acc[8][4] = {};
    const int NIT = K / 8;   // 96
    for (int t = 0; t < NIT; t++) {
        const int cur = t & 1;
        if (t + 1 < NIT) {
            const int k0 = (t + 1) * 8;
            av = (bm + ar < M) ? *(const float4*)&A[(size_t)(bm + ar) * K + k0 + ak]
                               : make_float4(0.f, 0.f, 0.f, 0.f);
            wv = *(const float4*)&W[(size_t)(k0 + wr) * K + bn + wc];
        }
#pragma unroll
        for (int kk = 0; kk < 8; kk++) {
            float4 a0 = *(const float4*)&As[cur][kk][tr * 8];
            float4 a1 = *(const float4*)&As[cur][kk][tr * 8 + 4];
            ulonglong2 b01 = *(const ulonglong2*)&Ws[cur][kk][tc * 8];
            ulonglong2 b23 = *(const ulonglong2*)&Ws[cur][kk][tc * 8 + 4];
            u64 ad[8] = {dup2(a0.x), dup2(a0.y), dup2(a0.z), dup2(a0.w),
                         dup2(a1.x), dup2(a1.y), dup2(a1.z), dup2(a1.w)};
#pragma unroll
            for (int ii = 0; ii < 8; ii++) {
                fma2(acc[ii][0], ad[ii], b01.x);
                fma2(acc[ii][1], ad[ii], b01.y);
                fma2(acc[ii][2], ad[ii], b23.x);
                fma2(acc[ii][3], ad[ii], b23.y);
            }
        }
        if (t + 1 < NIT) {
            const int nxt = cur ^ 1;
            As[nxt][ak + 0][ar] = av.x; As[nxt][ak + 1][ar] = av.y;
            As[nxt][ak + 2][ar] = av.z; As[nxt][ak + 3][ar] = av.w;
            *(float4*)&Ws[nxt][wr][wc] = wv;
        }
        __syncthreads();
    }

    float4 bv0 = *(const float4*)&bias[bn + tc * 8];
    float4 bv1 = *(const float4*)&bias[bn + tc * 8 + 4];
#pragma unroll
    for (int ii = 0; ii < 8; ii++) {
        const int m = bm + tr * 8 + ii;
        if (m < M) {
            float2 p0 = unpack2(acc[ii][0]);
            float2 p1 = unpack2(acc[ii][1]);
            float2 p2 = unpack2(acc[ii][2]);
            float2 p3 = unpack2(acc[ii][3]);
            float4 o0 = make_float4(p0.x + bv0.x, p0.y + bv0.y, p1.x + bv0.z, p1.y + bv0.w);
            float4 o1 = make_float4(p2.x + bv1.x, p2.y + bv1.y, p3.x + bv1.z, p3.y + bv1.w);
            *(float4*)&C[(size_t)m * 768 + bn + tc * 8]     = o0;
            *(float4*)&C[(size_t)m * 768 + bn + tc * 8 + 4] = o1;
        }
    }
}

// ============================================================================
// NT GEMM: T[1024,2048] = exp( (q@k^T)[i,j] * qinv[i] * kinv[j] * 10 )
// BM=BN=128, BK=8, 256 threads, 8x8 per thread via f32x2
// ============================================================================
__global__ void __launch_bounds__(256) gemm_nt_exp_kernel(
    const float* __restrict__ A, const float* __restrict__ Bk,
    const float* __restrict__ ainv, const float* __restrict__ binv,
    float* __restrict__ C)
{
    constexpr int K = 768, NN = 2048;
    __shared__ __align__(16) float As[2][8][128];
    __shared__ __align__(16) float Bs[2][8][128];

    const int tid = threadIdx.x;
    const int bm = blockIdx.y * 128;
    const int bn = blockIdx.x * 128;
    const int r  = tid >> 1;
    const int kc = (tid & 1) * 4;
    const int tr = tid >> 4;
    const int tc = tid & 15;

    float4 av = *(const float4*)&A [(size_t)(bm + r) * K + kc];
    float4 bv = *(const float4*)&Bk[(size_t)(bn + r) * K + kc];
    As[0][kc + 0][r] = av.x; As[0][kc + 1][r] = av.y;
    As[0][kc + 2][r] = av.z; As[0][kc + 3][r] = av.w;
    Bs[0][kc + 0][r] = bv.x; Bs[0][kc + 1][r] = bv.y;
    Bs[0][kc + 2][r] = bv.z; Bs[0][kc + 3][r] = bv.w;
    __syncthreads();

    u64 acc[8][4] = {};
    const int NIT = K / 8;
    for (int t = 0; t < NIT; t++) {
        const int cur = t & 1;
        if (t + 1 < NIT) {
            const int k0 = (t + 1) * 8;
            av = *(const float4*)&A [(size_t)(bm + r) * K + k0 + kc];
            bv = *(const float4*)&Bk[(size_t)(bn + r) * K + k0 + kc];
        }
#pragma unroll
        for (int kk = 0; kk < 8; kk++) {
            float4 a0 = *(const float4*)&As[cur][kk][tr * 8];
            float4 a1 = *(const float4*)&As[cur][kk][tr * 8 + 4];
            ulonglong2 b01 = *(const ulonglong2*)&Bs[cur][kk][tc * 8];
            ulonglong2 b23 = *(const ulonglong2*)&Bs[cur][kk][tc * 8 + 4];
            u64 ad[8] = {dup2(a0.x), dup2(a0.y), dup2(a0.z), dup2(a0.w),
                         dup2(a1.x), dup2(a1.y), dup2(a1.z), dup2(a1.w)};
#pragma unroll
            for (int ii = 0; ii < 8; ii++) {
                fma2(acc[ii][0], ad[ii], b01.x);
                fma2(acc[ii][1], ad[ii], b01.y);
                fma2(acc[ii][2], ad[ii], b23.x);
                fma2(acc[ii][3], ad[ii], b23.y);
            }
        }
        if (t + 1 < NIT) {
            const int nxt = cur ^ 1;
            As[nxt][kc + 0][r] = av.x; As[nxt][kc + 1][r] = av.y;
            As[nxt][kc + 2][r] = av.z; As[nxt][kc + 3][r] = av.w;
            Bs[nxt][kc + 0][r] = bv.x; Bs[nxt][kc + 1][r] = bv.y;
            Bs[nxt][kc + 2][r] = bv.z; Bs[nxt][kc + 3][r] = bv.w;
        }
        __syncthreads();
    }

    const int n0 = bn + tc * 8;
    float bi[8];
#pragma unroll
    for (int jj = 0; jj < 8; jj++) bi[jj] = binv[n0 + jj];
#pragma unroll
    for (int ii = 0; ii < 8; ii++) {
        const int m = bm + tr * 8 + ii;
        const float ai = ainv[m] * OT_INV_EPS;
        float2 p0 = unpack2(acc[ii][0]);
        float2 p1 = unpack2(acc[ii][1]);
        float2 p2 = unpack2(acc[ii][2]);
        float2 p3 = unpack2(acc[ii][3]);
        float4 o0, o1;
        o0.x = expf(p0.x * ai * bi[0]); o0.y = expf(p0.y * ai * bi[1]);
        o0.z = expf(p1.x * ai * bi[2]); o0.w = expf(p1.y * ai * bi[3]);
        o1.x = expf(p2.x * ai * bi[4]); o1.y = expf(p2.y * ai * bi[5]);
        o1.z = expf(p3.x * ai * bi[6]); o1.w = expf(p3.y * ai * bi[7]);
        *(float4*)&C[(size_t)m * NN + n0]     = o0;
        *(float4*)&C[(size_t)m * NN + n0 + 4] = o1;
    }
}

// ---------------- row L2-norm inverse (q and k fused) -----------------------
__global__ void rownorm_kernel(const float* __restrict__ q, const float* __restrict__ k,
                               float* __restrict__ qinv, float* __restrict__ kinv)
{
    int row = blockIdx.x * 8 + (threadIdx.x >> 5);
    int lane = threadIdx.x & 31;
    const float* x; float* inv;
    if (row < MQ) { x = q + (size_t)row * HD;        inv = qinv + row; }
    else          { x = k + (size_t)(row - MQ) * HD; inv = kinv + (row - MQ); }
    float s = 0.f;
#pragma unroll
    for (int p = 0; p < 6; p++) {
        float4 v4 = *(const float4*)&x[lane * 4 + p * 128];
        s += v4.x * v4.x + v4.y * v4.y + v4.z * v4.z + v4.w * v4.w;
    }
    s = warp_sum(s);
    if (lane == 0) *inv = 1.0f / fmaxf(sqrtf(s), 1e-8f);
}

// ---------------- Sinkhorn: per (a,b) 32x32 tile, warp-per-column reduce ----
__global__ void __launch_bounds__(1024) sinkhorn_kernel(
    const float* __restrict__ Tin, float* __restrict__ Tp)
{
    const int a = blockIdx.y, b = blockIdx.x;
    const int tid = threadIdx.x;
    const int i = tid >> 5, j = tid & 31;
    __shared__ float s[32 * 33];
    __shared__ float cs[32];

    float val = Tin[(size_t)(a * 32 + i) * MKV + b * 32 + j];
#pragma unroll 1
    for (int it = 0; it < 10; it++) {
        float rs = warp_sum(val);          // row sum (warp == row)
        val = __fdividef(val, rs);
        s[i * 33 + j] = val;
        __syncthreads();
        // warp i reduces column i: lane j reads s[j][i]
        float cv = s[j * 33 + i];
        float csum = warp_sum(cv);
        if (j == 0) cs[i] = csum;
        __syncthreads();
        val = __fdividef(val, cs[j]);
    }
    float n2 = warp_sum(val * val);
    val = __fdividef(val, fmaxf(sqrtf(n2), 1e-12f));
    Tp[(size_t)(a * 64 + b) * 1024 + i * 32 + j] = val;
}

// ------------- fused attend + LN1 + softpool + LN2 + scores ----------------
__global__ void __launch_bounds__(256) attend_kernel(
    const float* __restrict__ Tp, const float* __restrict__ q,
    const float* __restrict__ v, const float* __restrict__ ecls,
    const float* __restrict__ entity_cls, const float* __restrict__ mention_cls,
    const float* __restrict__ ln1_g, const float* __restrict__ ln1_b,
    const float* __restrict__ Wsp, const float* __restrict__ bsp,
    const float* __restrict__ ln2_g, const float* __restrict__ ln2_b,
    float* __restrict__ out)
{
    extern __shared__ float sm[];
    float* sv    = sm;             // 24576
    float* satt  = sv + 24576;     // 24576
    float* sTt   = satt + 24576;   // 32*36 = 1152 (transposed, padded)
    float* sWsp  = sTt + 1152;     // 768
    float* spool = sWsp + 768;     // 768
    float* sS    = spool + 768;    // 32
    float* sW    = sS + 32;        // 32
    float* sred  = sW + 32;        // 64

    const int a = blockIdx.y, b = blockIdx.x;
    const int tid = threadIdx.x, lane = tid & 31, wid = tid >> 5;

    // ---- loads
    const float* vb = v + (size_t)b * 32 * HD;
    for (int t = tid; t < 6144; t += 256)
        *(float4*)&sv[t * 4] = *(const float4*)&vb[t * 4];
    const float* Tb = Tp + (size_t)(a * 64 + b) * 1024;
    for (int t = tid; t < 1024; t += 256) {
        int i = t >> 5, j = t & 31;
        sTt[j * 36 + i] = Tb[t];
    }
    for (int t = tid; t < 768; t += 256) sWsp[t] = Wsp[t];
    __syncthreads();

    // ---- attended = T @ v_b + q_a   (8 rows x 4 cols f32x2 per thread-pass)
    {
        const int i0 = (wid & 3) * 8;
        const int dbase0 = (wid >> 2) * 384 + lane * 4;
        const float* qa = q + (size_t)(a * 32) * HD;
#pragma unroll 1
        for (int c = 0; c < 3; c++) {
            const int d = dbase0 + c * 128;
            u64 acc[8][2];
#pragma unroll
            for (int ii = 0; ii < 8; ii++) {
                ulonglong2 qv = *(const ulonglong2*)&qa[(i0 + ii) * HD + d];
                acc[ii][0] = qv.x; acc[ii][1] = qv.y;
            }
#pragma unroll 8
            for (int j = 0; j < 32; j++) {
                const ulonglong2 vv = *(const ulonglong2*)&sv[j * HD + d];
                float4 t0 = *(const float4*)&sTt[j * 36 + i0];
                float4 t1 = *(const float4*)&sTt[j * 36 + i0 + 4];
                u64 td[8] = {dup2(t0.x), dup2(t0.y), dup2(t0.z), dup2(t0.w),
                             dup2(t1.x), dup2(t1.y), dup2(t1.z), dup2(t1.w)};
#pragma unroll
                for (int ii = 0; ii < 8; ii++) {
                    fma2(acc[ii][0], td[ii], vv.x);
                    fma2(acc[ii][1], td[ii], vv.y);
                }
            }
#pragma unroll
            for (int ii = 0; ii < 8; ii++) {
                ulonglong2 o; o.x = acc[ii][0]; o.y = acc[ii][1];
                *(ulonglong2*)&satt[(i0 + ii) * HD + d] = o;
            }
        }
    }
    __syncthreads();

    // ---- LN1 per row + fused softpool score dot (warp per row, 4 rows/warp)
    const float bsp0 = bsp[0];
#pragma unroll 1
    for (int rr = 0; rr < 4; rr++) {
        const int i = wid + rr * 8;
        float* row = &satt[i * HD];
        float s = 0.f, sq = 0.f;
#pragma unroll
        for (int p = 0; p < 6; p++) {
            float4 x = *(float4*)&row[lane * 4 + p * 128];
            s += x.x + x.y + x.z + x.w;
            sq += x.x * x.x + x.y * x.y + x.z * x.z + x.w * x.w;
        }
        s = warp_sum(s); sq = warp_sum(sq);
        const float mean = s * (1.0f / HD);
        const float var = sq * (1.0f / HD) - mean * mean;
        const float rstd = rsqrtf(var + 1e-5f);
        float sc = 0.f;
#pragma unroll
        for (int p = 0; p < 6; p++) {
            const int d = lane * 4 + p * 128;
            float4 x  = *(float4*)&row[d];
            float4 g  = *(const float4*)&ln1_g[d];
            float4 bb = *(const float4*)&ln1_b[d];
            float4 w4 = *(const float4*)&sWsp[d];
            float4 y;
            y.x = (x.x - mean) * rstd * g.x + bb.x;
            y.y = (x.y - mean) * rstd * g.y + bb.y;
            y.z = (x.z - mean) * rstd * g.z + bb.z;
            y.w = (x.w - mean) * rstd * g.w + bb.w;
            *(float4*)&row[d] = y;
            sc += y.x * w4.x + y.y * w4.y + y.z * w4.z + y.w * w4.w;
        }
        sc = warp_sum(sc);
        if (lane == 0) sS[i] = sc + bsp0;
    }
    __syncthreads();

    // ---- softmax over 32 token scores (warp 0)
    if (wid == 0) {
        float sval = sS[lane];
        float mx = warp_max(sval);
        float e = expf(sval - mx);
        float sum = warp_sum(e);
        sW[lane] = e / sum;
    }
    __syncthreads();

    // ---- pooled[d] = sum_i w_i * LN1(att)[i,d]
    for (int d = tid; d < HD; d += 256) {
        float p = 0.f;
#pragma unroll
        for (int i = 0; i < 32; i++) p = fmaf(sW[i], satt[i * HD + d], p);
        spool[d] = p;
    }
    __syncthreads();

    // ---- LN2 over pooled (block reduce)
    float s = 0.f, sq = 0.f;
    for (int d = tid; d < HD; d += 256) {
        float x = spool[d];
        s += x; sq += x * x;
    }
    s = warp_sum(s); sq = warp_sum(sq);
    if (lane == 0) { sred[wid] = s; sred[8 + wid] = sq; }
    __syncthreads();
    if (tid == 0) {
        float ts = 0.f, tq = 0.f;
#pragma unroll
        for (int w = 0; w < 8; w++) { ts += sred[w]; tq += sred[8 + w]; }
        sred[16] = ts; sred[17] = tq;
    }
    __syncthreads();
    const float mean2 = sred[16] * (1.0f / HD);
    const float var2 = sred[17] * (1.0f / HD) - mean2 * mean2;
    const float rstd2 = rsqrtf(var2 + 1e-5f);

    // ---- g2l = ecls_a . LN2(pooled);  g2g = mention_cls_b . entity_cls_a
    const float* ea  = ecls + (size_t)a * HD;
    const float* eca = entity_cls + (size_t)a * HD;
    const float* mcb = mention_cls + (size_t)b * HD;
    float g2l = 0.f, g2g = 0.f;
    for (int d = tid; d < HD; d += 256) {
        float ctx = (spool[d] - mean2) * rstd2 * ln2_g[d] + ln2_b[d];
        g2l = fmaf(ea[d], ctx, g2l);
        g2g = fmaf(eca[d], mcb[d], g2g);
    }
    g2l = warp_sum(g2l); g2g = warp_sum(g2g);
    __syncthreads();
    if (lane == 0) { sred[wid] = g2l; sred[8 + wid] = g2g; }
    __syncthreads();
    if (tid == 0) {
        float tl = 0.f, tg = 0.f;
#pragma unroll
        for (int w = 0; w < 8; w++) { tl += sred[w]; tg += sred[8 + w]; }
        out[b * NA + a] = 0.5f * (tl + tg);
    }
}

// ---------------------------------------------------------------------------
extern "C" void kernel_launch(void* const* d_in, const int* in_sizes, int n_in,
                              void* d_out, int out_size)
{
    const float* entity_cls     = (const float*)d_in[0];
    const float* entity_tokens  = (const float*)d_in[1];
    const float* mention_cls    = (const float*)d_in[2];
    const float* mention_tokens = (const float*)d_in[3];
    const float* Wq   = (const float*)d_in[4];
    const float* bq   = (const float*)d_in[5];
    const float* Wk   = (const float*)d_in[6];
    const float* bk   = (const float*)d_in[7];
    const float* Wv   = (const float*)d_in[8];
    const float* bv   = (const float*)d_in[9];
    const float* ln1g = (const float*)d_in[10];
    const float* ln1b = (const float*)d_in[11];
    const float* Wcls = (const float*)d_in[12];
    const float* bcls = (const float*)d_in[13];
    const float* Wsp  = (const float*)d_in[14];
    const float* bsp  = (const float*)d_in[15];
    const float* ln2g = (const float*)d_in[16];
    const float* ln2b = (const float*)d_in[17];
    float* out = (float*)d_out;

    float *pq, *pk, *pv, *pecls, *pqinv, *pkinv, *pT, *pTp;
    cudaGetSymbolAddress((void**)&pq,    g_q);
    cudaGetSymbolAddress((void**)&pk,    g_k);
    cudaGetSymbolAddress((void**)&pv,    g_v);
    cudaGetSymbolAddress((void**)&pecls, g_ecls);
    cudaGetSymbolAddress((void**)&pqinv, g_qinv);
    cudaGetSymbolAddress((void**)&pkinv, g_kinv);
    cudaGetSymbolAddress((void**)&pT,    g_T);
    cudaGetSymbolAddress((void**)&pTp,   g_Tp);

    // all 4 projection GEMMs in one launch
    proj_kernel<<<dim3(6, 16, 4), 256>>>(
        entity_tokens, mention_tokens, entity_cls,
        Wq, bq, Wk, bk, Wv, bv, Wcls, bcls);

    // inverse row norms (q and k fused)
    rownorm_kernel<<<(MQ + MKV) / 8, 256>>>(pq, pk, pqinv, pkinv);

    // cosine-sim GEMM fused with exp(C/eps)
    gemm_nt_exp_kernel<<<dim3(16, 8), 256>>>(pq, pk, pqinv, pkinv, pT);

    // Sinkhorn + final L2 row normalize; writes tile-packed layout
    sinkhorn_kernel<<<dim3(BB, NA), 1024>>>(pT, pTp);

    // fused attend / LN1 / softpool / LN2 / scores / g2g
    const int smem_bytes = (24576 + 24576 + 1152 + 768 + 768 + 32 + 32 + 64) * 4;
    cudaFuncSetAttribute(attend_kernel, cudaFuncAttributeMaxDynamicSharedMemorySize, smem_bytes);
    attend_kernel<<<dim3(BB, NA), 256, smem_bytes>>>(
        pTp, pq, pv, pecls, entity_cls, mention_cls,
        ln1g, ln1b, Wsp, bsp, ln2g, ln2b, out);
}

// round 3
// speedup vs baseline: 1.6557x; 1.1705x over previous
#include <cuda_runtime.h>
#include <math.h>

#define NA   32
#define LA   32
#define BB   64
#define LBD  32
#define DIN  768
#define HD   768
#define MQ   (NA*LA)     // 1024
#define MKV  (BB*LBD)    // 2048
#define OT_INV_EPS 10.0f

typedef unsigned long long u64;

// ---------------- scratch (device globals; no allocation allowed) ----------
__device__ float g_q[MQ*HD];        // 3 MB
__device__ float g_k[MKV*HD];       // 6 MB
__device__ float g_v[MKV*HD];       // 6 MB
__device__ float g_ecls[NA*HD];
__device__ float g_qinv[MQ];
__device__ float g_kinv[MKV];
__device__ float g_T[MQ*MKV];       // 8 MB  exp(C/eps), row-major
__device__ float g_Tp[MQ*MKV];      // 8 MB  sinkhorn output, tile-packed

// ---------------- f32x2 packed-math helpers --------------------------------
__device__ __forceinline__ u64 dup2(float x) {
    u64 r; asm("mov.b64 %0, {%1, %1};" : "=l"(r) : "f"(x)); return r;
}
__device__ __forceinline__ void fma2(u64 &d, u64 a, u64 b) {
    asm("fma.rn.f32x2 %0, %1, %2, %0;" : "+l"(d) : "l"(a), "l"(b));
}
__device__ __forceinline__ float2 unpack2(u64 v) {
    float2 r; asm("mov.b64 {%0, %1}, %2;" : "=f"(r.x), "=f"(r.y) : "l"(v)); return r;
}

__device__ __forceinline__ float warp_sum(float x) {
#pragma unroll
    for (int o = 16; o > 0; o >>= 1) x += __shfl_xor_sync(0xffffffffu, x, o);
    return x;
}
__device__ __forceinline__ float warp_max(float x) {
#pragma unroll
    for (int o = 16; o > 0; o >>= 1) x = fmaxf(x, __shfl_xor_sync(0xffffffffu, x, o));
    return x;
}

// ============================================================================
// Fused projection GEMMs (NN): C[M,768] = A[M,768] @ W[768,768] + bias
// z=0: q   z=1: k   z=2: v   z=3: ecls
// BM=BN=128, BK=8, 256 threads, 8x8 per thread via f32x2
// ============================================================================
__global__ void __launch_bounds__(256) proj_kernel(
    const float* __restrict__ entity_tokens, const float* __restrict__ mention_tokens,
    const float* __restrict__ entity_cls,
    const float* __restrict__ Wq, const float* __restrict__ bq,
    const float* __restrict__ Wk, const float* __restrict__ bk,
    const float* __restrict__ Wv, const float* __restrict__ bv,
    const float* __restrict__ Wcls, const float* __restrict__ bcls)
{
    const float* A; const float* W; const float* bias; float* C; int M;
    switch (blockIdx.z) {
        case 0: if (blockIdx.y >= 8) return;
                A = entity_tokens;  W = Wq;   bias = bq;   C = g_q;    M = MQ;  break;
        case 1: A = mention_tokens; W = Wk;   bias = bk;   C = g_k;    M = MKV; break;
        case 2: A = mention_tokens; W = Wv;   bias = bv;   C = g_v;    M = MKV; break;
        default: if (blockIdx.y >= 1) return;
                A = entity_cls;     W = Wcls; bias = bcls; C = g_ecls; M = NA;  break;
    }
    constexpr int K = 768;
    __shared__ __align__(16) float As[2][8][128];
    __shared__ __align__(16) float Ws[2][8][128];

    const int tid = threadIdx.x;
    const int bm = blockIdx.y * 128;
    const int bn = blockIdx.x * 128;
    const int ar = tid >> 1;            // A row within tile 0..127
    const int ak = (tid & 1) * 4;       // A k within BK: 0 or 4
    const int wr = tid >> 5;            // W row within BK 0..7
    const int wc = (tid & 31) * 4;      // W col 0..124
    const int tr = tid >> 4;            // 0..15
    const int tc = tid & 15;            // 0..15

    float4 av, wv;
    av = (bm + ar < M) ? *(const float4*)&A[(size_t)(bm + ar) * K + ak]
                       : make_float4(0.f, 0.f, 0.f, 0.f);
    wv = *(const float4*)&W[(size_t)wr * K + bn + wc];
    As[0][ak + 0][ar] = av.x; As[0][ak + 1][ar] = av.y;
    As[0][ak + 2][ar] = av.z; As[0][ak + 3][ar] = av.w;
    *(float4*)&Ws[0][wr][wc] = wv;
    __syncthreads();

    u64 acc[8][4] = {};
    const int NIT = K / 8;   // 96
    for (int t = 0; t < NIT; t++) {
        const int cur = t & 1;
        if (t + 1 < NIT) {
            const int k0 = (t + 1) * 8;
            av = (bm + ar < M) ? *(const float4*)&A[(size_t)(bm + ar) * K + k0 + ak]
                               : make_float4(0.f, 0.f, 0.f, 0.f);
            wv = *(const float4*)&W[(size_t)(k0 + wr) * K + bn + wc];
        }
#pragma unroll
        for (int kk = 0; kk < 8; kk++) {
            float4 a0 = *(const float4*)&As[cur][kk][tr * 8];
            float4 a1 = *(const float4*)&As[cur][kk][tr * 8 + 4];
            ulonglong2 b01 = *(const ulonglong2*)&Ws[cur][kk][tc * 8];
            ulonglong2 b23 = *(const ulonglong2*)&Ws[cur][kk][tc * 8 + 4];
            u64 ad[8] = {dup2(a0.x), dup2(a0.y), dup2(a0.z), dup2(a0.w),
                         dup2(a1.x), dup2(a1.y), dup2(a1.z), dup2(a1.w)};
#pragma unroll
            for (int ii = 0; ii < 8; ii++) {
                fma2(acc[ii][0], ad[ii], b01.x);
                fma2(acc[ii][1], ad[ii], b01.y);
                fma2(acc[ii][2], ad[ii], b23.x);
                fma2(acc[ii][3], ad[ii], b23.y);
            }
        }
        if (t + 1 < NIT) {
            const int nxt = cur ^ 1;
            As[nxt][ak + 0][ar] = av.x; As[nxt][ak + 1][ar] = av.y;
            As[nxt][ak + 2][ar] = av.z; As[nxt][ak + 3][ar] = av.w;
            *(float4*)&Ws[nxt][wr][wc] = wv;
        }
        __syncthreads();
    }

    float4 bv0 = *(const float4*)&bias[bn + tc * 8];
    float4 bv1 = *(const float4*)&bias[bn + tc * 8 + 4];
#pragma unroll
    for (int ii = 0; ii < 8; ii++) {
        const int m = bm + tr * 8 + ii;
        if (m < M) {
            float2 p0 = unpack2(acc[ii][0]);
            float2 p1 = unpack2(acc[ii][1]);
            float2 p2 = unpack2(acc[ii][2]);
            float2 p3 = unpack2(acc[ii][3]);
            float4 o0 = make_float4(p0.x + bv0.x, p0.y + bv0.y, p1.x + bv0.z, p1.y + bv0.w);
            float4 o1 = make_float4(p2.x + bv1.x, p2.y + bv1.y, p3.x + bv1.z, p3.y + bv1.w);
            *(float4*)&C[(size_t)m * 768 + bn + tc * 8]     = o0;
            *(float4*)&C[(size_t)m * 768 + bn + tc * 8 + 4] = o1;
        }
    }
}

// ============================================================================
// NT GEMM: T[1024,2048] = exp( (q@k^T)[i,j] * qinv[i] * kinv[j] * 10 )
// ============================================================================
__global__ void __launch_bounds__(256) gemm_nt_exp_kernel(
    const float* __restrict__ A, const float* __restrict__ Bk,
    const float* __restrict__ ainv, const float* __restrict__ binv,
    float* __restrict__ C)
{
    constexpr int K = 768, NN = 2048;
    __shared__ __align__(16) float As[2][8][128];
    __shared__ __align__(16) float Bs[2][8][128];

    const int tid = threadIdx.x;
    const int bm = blockIdx.y * 128;
    const int bn = blockIdx.x * 128;
    const int r  = tid >> 1;
    const int kc = (tid & 1) * 4;
    const int tr = tid >> 4;
    const int tc = tid & 15;

    float4 av = *(const float4*)&A [(size_t)(bm + r) * K + kc];
    float4 bv = *(const float4*)&Bk[(size_t)(bn + r) * K + kc];
    As[0][kc + 0][r] = av.x; As[0][kc + 1][r] = av.y;
    As[0][kc + 2][r] = av.z; As[0][kc + 3][r] = av.w;
    Bs[0][kc + 0][r] = bv.x; Bs[0][kc + 1][r] = bv.y;
    Bs[0][kc + 2][r] = bv.z; Bs[0][kc + 3][r] = bv.w;
    __syncthreads();

    u64 acc[8][4] = {};
    const int NIT = K / 8;
    for (int t = 0; t < NIT; t++) {
        const int cur = t & 1;
        if (t + 1 < NIT) {
            const int k0 = (t + 1) * 8;
            av = *(const float4*)&A [(size_t)(bm + r) * K + k0 + kc];
            bv = *(const float4*)&Bk[(size_t)(bn + r) * K + k0 + kc];
        }
#pragma unroll
        for (int kk = 0; kk < 8; kk++) {
            float4 a0 = *(const float4*)&As[cur][kk][tr * 8];
            float4 a1 = *(const float4*)&As[cur][kk][tr * 8 + 4];
            ulonglong2 b01 = *(const ulonglong2*)&Bs[cur][kk][tc * 8];
            ulonglong2 b23 = *(const ulonglong2*)&Bs[cur][kk][tc * 8 + 4];
            u64 ad[8] = {dup2(a0.x), dup2(a0.y), dup2(a0.z), dup2(a0.w),
                         dup2(a1.x), dup2(a1.y), dup2(a1.z), dup2(a1.w)};
#pragma unroll
            for (int ii = 0; ii < 8; ii++) {
                fma2(acc[ii][0], ad[ii], b01.x);
                fma2(acc[ii][1], ad[ii], b01.y);
                fma2(acc[ii][2], ad[ii], b23.x);
                fma2(acc[ii][3], ad[ii], b23.y);
            }
        }
        if (t + 1 < NIT) {
            const int nxt = cur ^ 1;
            As[nxt][kc + 0][r] = av.x; As[nxt][kc + 1][r] = av.y;
            As[nxt][kc + 2][r] = av.z; As[nxt][kc + 3][r] = av.w;
            Bs[nxt][kc + 0][r] = bv.x; Bs[nxt][kc + 1][r] = bv.y;
            Bs[nxt][kc + 2][r] = bv.z; Bs[nxt][kc + 3][r] = bv.w;
        }
        __syncthreads();
    }

    const int n0 = bn + tc * 8;
    float bi[8];
#pragma unroll
    for (int jj = 0; jj < 8; jj++) bi[jj] = binv[n0 + jj];
#pragma unroll
    for (int ii = 0; ii < 8; ii++) {
        const int m = bm + tr * 8 + ii;
        const float ai = ainv[m] * OT_INV_EPS;
        float2 p0 = unpack2(acc[ii][0]);
        float2 p1 = unpack2(acc[ii][1]);
        float2 p2 = unpack2(acc[ii][2]);
        float2 p3 = unpack2(acc[ii][3]);
        float4 o0, o1;
        o0.x = expf(p0.x * ai * bi[0]); o0.y = expf(p0.y * ai * bi[1]);
        o0.z = expf(p1.x * ai * bi[2]); o0.w = expf(p1.y * ai * bi[3]);
        o1.x = expf(p2.x * ai * bi[4]); o1.y = expf(p2.y * ai * bi[5]);
        o1.z = expf(p3.x * ai * bi[6]); o1.w = expf(p3.y * ai * bi[7]);
        *(float4*)&C[(size_t)m * NN + n0]     = o0;
        *(float4*)&C[(size_t)m * NN + n0 + 4] = o1;
    }
}

// ---------------- row L2-norm inverse (q and k fused) -----------------------
__global__ void rownorm_kernel(const float* __restrict__ q, const float* __restrict__ k,
                               float* __restrict__ qinv, float* __restrict__ kinv)
{
    int row = blockIdx.x * 8 + (threadIdx.x >> 5);
    int lane = threadIdx.x & 31;
    const float* x; float* inv;
    if (row < MQ) { x = q + (size_t)row * HD;        inv = qinv + row; }
    else          { x = k + (size_t)(row - MQ) * HD; inv = kinv + (row - MQ); }
    float s = 0.f;
#pragma unroll
    for (int p = 0; p < 6; p++) {
        float4 v4 = *(const float4*)&x[lane * 4 + p * 128];
        s += v4.x * v4.x + v4.y * v4.y + v4.z * v4.z + v4.w * v4.w;
    }
    s = warp_sum(s);
    if (lane == 0) *inv = 1.0f / fmaxf(sqrtf(s), 1e-8f);
}

// ============================================================================
// Sinkhorn: warp-per-tile, all-register. lane = row i, r[j] = tile[i][j].
// Row sums: in-register reduction. Col sums: 5-round butterfly on the vector.
// Writes tile-packed layout for the attend kernel.
// ============================================================================
__global__ void __launch_bounds__(256) sinkhorn_kernel(
    const float* __restrict__ Tin, float* __restrict__ Tp)
{
    const int tile = blockIdx.x * 8 + (threadIdx.x >> 5);   // 0..2047
    const int a = tile >> 6, b = tile & 63;
    const int lane = threadIdx.x & 31;

    const float* src = Tin + (size_t)(a * 32 + lane) * MKV + b * 32;
    float r[32];
#pragma unroll
    for (int p = 0; p < 8; p++) {
        float4 v4 = *(const float4*)&src[p * 4];
        r[p * 4 + 0] = v4.x; r[p * 4 + 1] = v4.y;
        r[p * 4 + 2] = v4.z; r[p * 4 + 3] = v4.w;
    }

#pragma unroll 1
    for (int it = 0; it < 10; it++) {
        // --- row normalize (axis -1): per-lane register reduction
        float rs = 0.f;
#pragma unroll
        for (int j = 0; j < 32; j++) rs += r[j];
        float rinv = __fdividef(1.0f, rs);
#pragma unroll
        for (int j = 0; j < 32; j++) r[j] *= rinv;

        // --- column sums (axis -2): butterfly across lanes on the whole vector
        float t[32];
#pragma unroll
        for (int j = 0; j < 32; j++) t[j] = r[j];
#pragma unroll
        for (int o = 16; o > 0; o >>= 1) {
#pragma unroll
            for (int j = 0; j < 32; j++)
                t[j] += __shfl_xor_sync(0xffffffffu, t[j], o);
        }
#pragma unroll
        for (int j = 0; j < 32; j++) r[j] = __fdividef(r[j], t[j]);
    }

    // --- final L2 row-normalize
    float n2 = 0.f;
#pragma unroll
    for (int j = 0; j < 32; j++) n2 = fmaf(r[j], r[j], n2);
    float ninv = __fdividef(1.0f, fmaxf(sqrtf(n2), 1e-12f));
#pragma unroll
    for (int j = 0; j < 32; j++) r[j] *= ninv;

    float* dst = Tp + (size_t)tile * 1024 + lane * 32;
#pragma unroll
    for (int p = 0; p < 8; p++)
        *(float4*)&dst[p * 4] = make_float4(r[p * 4], r[p * 4 + 1], r[p * 4 + 2], r[p * 4 + 3]);
}

// ============================================================================
// fused attend + LN1 + softpool + LN2 + scores.
// v is read directly from L2 (zero smem reuse) -> smem small enough for
// 2 CTAs/SM (halves wave count, hides load latency).
// ============================================================================
__global__ void __launch_bounds__(256, 2) attend_kernel(
    const float* __restrict__ Tp, const float* __restrict__ q,
    const float* __restrict__ v, const float* __restrict__ ecls,
    const float* __restrict__ entity_cls, const float* __restrict__ mention_cls,
    const float* __restrict__ ln1_g, const float* __restrict__ ln1_b,
    const float* __restrict__ Wsp, const float* __restrict__ bsp,
    const float* __restrict__ ln2_g, const float* __restrict__ ln2_b,
    float* __restrict__ out)
{
    extern __shared__ float sm[];
    float* satt  = sm;             // 24576
    float* sTt   = satt + 24576;   // 32*36 = 1152 (transposed, padded)
    float* sWsp  = sTt + 1152;     // 768
    float* spool = sWsp + 768;     // 768
    float* sS    = spool + 768;    // 32
    float* sW    = sS + 32;        // 32
    float* sred  = sW + 32;        // 64

    const int a = blockIdx.y, b = blockIdx.x;
    const int tid = threadIdx.x, lane = tid & 31, wid = tid >> 5;

    // ---- small loads (T tile transposed, Wsp)
    const float* Tb = Tp + (size_t)(a * 64 + b) * 1024;
    for (int t = tid; t < 1024; t += 256) {
        int i = t >> 5, j = t & 31;
        sTt[j * 36 + i] = Tb[t];
    }
    for (int t = tid; t < 768; t += 256) sWsp[t] = Wsp[t];
    __syncthreads();

    // ---- attended = T @ v_b + q_a   (v streamed from L2)
    {
        const int i0 = (wid & 3) * 8;
        const int dbase0 = (wid >> 2) * 384 + lane * 4;
        const float* qa = q + (size_t)(a * 32) * HD;
        const float* vb = v + (size_t)b * 32 * HD;
#pragma unroll 1
        for (int c = 0; c < 3; c++) {
            const int d = dbase0 + c * 128;
            u64 acc[8][2];
#pragma unroll
            for (int ii = 0; ii < 8; ii++) {
                ulonglong2 qv = *(const ulonglong2*)&qa[(i0 + ii) * HD + d];
                acc[ii][0] = qv.x; acc[ii][1] = qv.y;
            }
#pragma unroll 8
            for (int j = 0; j < 32; j++) {
                const ulonglong2 vv = *(const ulonglong2*)&vb[(size_t)j * HD + d];
                float4 t0 = *(const float4*)&sTt[j * 36 + i0];
                float4 t1 = *(const float4*)&sTt[j * 36 + i0 + 4];
                u64 td[8] = {dup2(t0.x), dup2(t0.y), dup2(t0.z), dup2(t0.w),
                             dup2(t1.x), dup2(t1.y), dup2(t1.z), dup2(t1.w)};
#pragma unroll
                for (int ii = 0; ii < 8; ii++) {
                    fma2(acc[ii][0], td[ii], vv.x);
                    fma2(acc[ii][1], td[ii], vv.y);
                }
            }
#pragma unroll
            for (int ii = 0; ii < 8; ii++) {
                ulonglong2 o; o.x = acc[ii][0]; o.y = acc[ii][1];
                *(ulonglong2*)&satt[(i0 + ii) * HD + d] = o;
            }
        }
    }
    __syncthreads();

    // ---- LN1 per row + fused softpool score dot (warp per row, 4 rows/warp)
    const float bsp0 = bsp[0];
#pragma unroll 1
    for (int rr = 0; rr < 4; rr++) {
        const int i = wid + rr * 8;
        float* row = &satt[i * HD];
        float s = 0.f, sq = 0.f;
#pragma unroll
        for (int p = 0; p < 6; p++) {
            float4 x = *(float4*)&row[lane * 4 + p * 128];
            s += x.x + x.y + x.z + x.w;
            sq += x.x * x.x + x.y * x.y + x.z * x.z + x.w * x.w;
        }
        s = warp_sum(s); sq = warp_sum(sq);
        const float mean = s * (1.0f / HD);
        const float var = sq * (1.0f / HD) - mean * mean;
        const float rstd = rsqrtf(var + 1e-5f);
        float sc = 0.f;
#pragma unroll
        for (int p = 0; p < 6; p++) {
            const int d = lane * 4 + p * 128;
            float4 x  = *(float4*)&row[d];
            float4 g  = *(const float4*)&ln1_g[d];
            float4 bb = *(const float4*)&ln1_b[d];
            float4 w4 = *(const float4*)&sWsp[d];
            float4 y;
            y.x = (x.x - mean) * rstd * g.x + bb.x;
            y.y = (x.y - mean) * rstd * g.y + bb.y;
            y.z = (x.z - mean) * rstd * g.z + bb.z;
            y.w = (x.w - mean) * rstd * g.w + bb.w;
            *(float4*)&row[d] = y;
            sc += y.x * w4.x + y.y * w4.y + y.z * w4.z + y.w * w4.w;
        }
        sc = warp_sum(sc);
        if (lane == 0) sS[i] = sc + bsp0;
    }
    __syncthreads();

    // ---- softmax over 32 token scores (warp 0)
    if (wid == 0) {
        float sval = sS[lane];
        float mx = warp_max(sval);
        float e = expf(sval - mx);
        float sum = warp_sum(e);
        sW[lane] = e / sum;
    }
    __syncthreads();

    // ---- pooled[d] = sum_i w_i * LN1(att)[i,d]
    for (int d = tid; d < HD; d += 256) {
        float p = 0.f;
#pragma unroll
        for (int i = 0; i < 32; i++) p = fmaf(sW[i], satt[i * HD + d], p);
        spool[d] = p;
    }
    __syncthreads();

    // ---- LN2 over pooled (block reduce)
    float s = 0.f, sq = 0.f;
    for (int d = tid; d < HD; d += 256) {
        float x = spool[d];
        s += x; sq += x * x;
    }
    s = warp_sum(s); sq = warp_sum(sq);
    if (lane == 0) { sred[wid] = s; sred[8 + wid] = sq; }
    __syncthreads();
    if (tid == 0) {
        float ts = 0.f, tq = 0.f;
#pragma unroll
        for (int w = 0; w < 8; w++) { ts += sred[w]; tq += sred[8 + w]; }
        sred[16] = ts; sred[17] = tq;
    }
    __syncthreads();
    const float mean2 = sred[16] * (1.0f / HD);
    const float var2 = sred[17] * (1.0f / HD) - mean2 * mean2;
    const float rstd2 = rsqrtf(var2 + 1e-5f);

    // ---- g2l = ecls_a . LN2(pooled);  g2g = mention_cls_b . entity_cls_a
    const float* ea  = ecls + (size_t)a * HD;
    const float* eca = entity_cls + (size_t)a * HD;
    const float* mcb = mention_cls + (size_t)b * HD;
    float g2l = 0.f, g2g = 0.f;
    for (int d = tid; d < HD; d += 256) {
        float ctx = (spool[d] - mean2) * rstd2 * ln2_g[d] + ln2_b[d];
        g2l = fmaf(ea[d], ctx, g2l);
        g2g = fmaf(eca[d], mcb[d], g2g);
    }
    g2l = warp_sum(g2l); g2g = warp_sum(g2g);
    __syncthreads();
    if (lane == 0) { sred[wid] = g2l; sred[8 + wid] = g2g; }
    __syncthreads();
    if (tid == 0) {
        float tl = 0.f, tg = 0.f;
#pragma unroll
        for (int w = 0; w < 8; w++) { tl += sred[w]; tg += sred[8 + w]; }
        out[b * NA + a] = 0.5f * (tl + tg);
    }
}

// ---------------------------------------------------------------------------
extern "C" void kernel_launch(void* const* d_in, const int* in_sizes, int n_in,
                              void* d_out, int out_size)
{
    const float* entity_cls     = (const float*)d_in[0];
    const float* entity_tokens  = (const float*)d_in[1];
    const float* mention_cls    = (const float*)d_in[2];
    const float* mention_tokens = (const float*)d_in[3];
    const float* Wq   = (const float*)d_in[4];
    const float* bq   = (const float*)d_in[5];
    const float* Wk   = (const float*)d_in[6];
    const float* bk   = (const float*)d_in[7];
    const float* Wv   = (const float*)d_in[8];
    const float* bv   = (const float*)d_in[9];
    const float* ln1g = (const float*)d_in[10];
    const float* ln1b = (const float*)d_in[11];
    const float* Wcls = (const float*)d_in[12];
    const float* bcls = (const float*)d_in[13];
    const float* Wsp  = (const float*)d_in[14];
    const float* bsp  = (const float*)d_in[15];
    const float* ln2g = (const float*)d_in[16];
    const float* ln2b = (const float*)d_in[17];
    float* out = (float*)d_out;

    float *pq, *pk, *pv, *pecls, *pqinv, *pkinv, *pT, *pTp;
    cudaGetSymbolAddress((void**)&pq,    g_q);
    cudaGetSymbolAddress((void**)&pk,    g_k);
    cudaGetSymbolAddress((void**)&pv,    g_v);
    cudaGetSymbolAddress((void**)&pecls, g_ecls);
    cudaGetSymbolAddress((void**)&pqinv, g_qinv);
    cudaGetSymbolAddress((void**)&pkinv, g_kinv);
    cudaGetSymbolAddress((void**)&pT,    g_T);
    cudaGetSymbolAddress((void**)&pTp,   g_Tp);

    // all 4 projection GEMMs in one launch
    proj_kernel<<<dim3(6, 16, 4), 256>>>(
        entity_tokens, mention_tokens, entity_cls,
        Wq, bq, Wk, bk, Wv, bv, Wcls, bcls);

    // inverse row norms (q and k fused)
    rownorm_kernel<<<(MQ + MKV) / 8, 256>>>(pq, pk, pqinv, pkinv);

    // cosine-sim GEMM fused with exp(C/eps)
    gemm_nt_exp_kernel<<<dim3(16, 8), 256>>>(pq, pk, pqinv, pkinv, pT);

    // Sinkhorn + final L2 row normalize; writes tile-packed layout
    sinkhorn_kernel<<<256, 256>>>(pT, pTp);

    // fused attend / LN1 / softpool / LN2 / scores / g2g (2 CTAs/SM)
    const int smem_bytes = (24576 + 1152 + 768 + 768 + 32 + 32 + 64) * 4;
    cudaFuncSetAttribute(attend_kernel, cudaFuncAttributeMaxDynamicSharedMemorySize, smem_bytes);
    attend_kernel<<<dim3(BB, NA), 256, smem_bytes>>>(
        pTp, pq, pv, pecls, entity_cls, mention_cls,
        ln1g, ln1b, Wsp, bsp, ln2g, ln2b, out);
}

// round 5
// speedup vs baseline: 2.7845x; 1.6818x over previous
#include <cuda_runtime.h>
#include <cuda_bf16.h>
#include <math.h>
#include <stdint.h>

#define NA   32
#define LA   32
#define BB   64
#define LBD  32
#define DIN  768
#define HD   768
#define MQ   (NA*LA)     // 1024
#define MKV  (BB*LBD)    // 2048
#define OT_INV_EPS 10.0f

typedef unsigned long long u64;
typedef __nv_bfloat16 bf16;

// ---------------- scratch (device globals; no allocation allowed) ----------
__device__ float g_q[MQ*HD];
__device__ float g_k[MKV*HD];
__device__ float g_v[MKV*HD];
__device__ float g_ecls[NA*HD];
__device__ float g_qinv[MQ];
__device__ float g_kinv[MKV];
__device__ float g_T[MQ*MKV];
__device__ float g_Tp[MQ*MKV];
// bf16 hi/lo operands
__device__ __align__(16) bf16 g_qh[MQ*HD];
__device__ __align__(16) bf16 g_ql[MQ*HD];
__device__ __align__(16) bf16 g_kh[MKV*HD];
__device__ __align__(16) bf16 g_kl[MKV*HD];
__device__ __align__(16) bf16 g_eth[MQ*DIN],  g_etl[MQ*DIN];    // entity_tokens
__device__ __align__(16) bf16 g_mth[MKV*DIN], g_mtl[MKV*DIN];   // mention_tokens
__device__ __align__(16) bf16 g_ech[NA*DIN],  g_ecl[NA*DIN];    // entity_cls
__device__ __align__(16) bf16 g_wqh[HD*DIN],  g_wql[HD*DIN];    // W^T hi/lo ([n][k])
__device__ __align__(16) bf16 g_wkh[HD*DIN],  g_wkl[HD*DIN];
__device__ __align__(16) bf16 g_wvh[HD*DIN],  g_wvl[HD*DIN];
__device__ __align__(16) bf16 g_wch[HD*DIN],  g_wcl[HD*DIN];

// ---------------- f32x2 packed-math helpers (attend kernel) ----------------
__device__ __forceinline__ u64 dup2(float x) {
    u64 r; asm("mov.b64 %0, {%1, %1};" : "=l"(r) : "f"(x)); return r;
}
__device__ __forceinline__ void fma2(u64 &d, u64 a, u64 b) {
    asm("fma.rn.f32x2 %0, %1, %2, %0;" : "+l"(d) : "l"(a), "l"(b));
}
__device__ __forceinline__ float warp_sum(float x) {
#pragma unroll
    for (int o = 16; o > 0; o >>= 1) x += __shfl_xor_sync(0xffffffffu, x, o);
    return x;
}
__device__ __forceinline__ float warp_max(float x) {
#pragma unroll
    for (int o = 16; o > 0; o >>= 1) x = fmaxf(x, __shfl_xor_sync(0xffffffffu, x, o));
    return x;
}

// ---------------- mma.sync / ldmatrix / cp.async helpers -------------------
__device__ __forceinline__ uint32_t smem_u32(const void* p) {
    uint32_t a;
    asm("{ .reg .u64 t; cvta.to.shared.u64 t, %1; cvt.u32.u64 %0, t; }"
        : "=r"(a) : "l"(p));
    return a;
}
__device__ __forceinline__ void ldsm4(uint32_t* r, uint32_t addr) {
    asm volatile("ldmatrix.sync.aligned.m8n8.x4.shared.b16 {%0,%1,%2,%3}, [%4];"
        : "=r"(r[0]), "=r"(r[1]), "=r"(r[2]), "=r"(r[3]) : "r"(addr));
}
__device__ __forceinline__ void mma_bf16(float* c, const uint32_t* a, const uint32_t* b) {
    asm volatile(
        "mma.sync.aligned.m16n8k16.row.col.f32.bf16.bf16.f32 "
        "{%0,%1,%2,%3}, {%4,%5,%6,%7}, {%8,%9}, {%0,%1,%2,%3};"
        : "+f"(c[0]), "+f"(c[1]), "+f"(c[2]), "+f"(c[3])
        : "r"(a[0]), "r"(a[1]), "r"(a[2]), "r"(a[3]), "r"(b[0]), "r"(b[1]));
}
#define CPA(sm, gm) \
    asm volatile("cp.async.ca.shared.global [%0], [%1], 16;" :: "r"(sm), "l"(gm))
#define CPA_COMMIT() asm volatile("cp.async.commit_group;" ::: "memory")
#define CPA_WAIT0()  asm volatile("cp.async.wait_group 0;" ::: "memory")

// smem geometry: 4 tiles (Ah,Al,Bh,Bl), each 128 rows x 32 bf16, row stride 40 elem (80 B)
#define TILE_B   10240              // bytes per tile
#define BUF_B    40960              // bytes per stage buffer
#define SMEM_MMA (2 * BUF_B)        // 81920

// ---- cp.async one BK=32 stage ----------------------------------------------
__device__ __forceinline__ void issue_stage(
    const bf16* Ah, const bf16* Al, const bf16* Bh, const bf16* Bl,
    int aRow0, int aMax, int bRow0, uint32_t sbase, int k0, int buf, int tid)
{
#pragma unroll
    for (int i = 0; i < 8; i++) {
        const int c = tid + i * 256;
        const int tile = c >> 9, cc = c & 511, row = cc >> 2, ch = cc & 3;
        const bf16* src;
        if (tile == 0)      src = Ah + (size_t)min(aRow0 + row, aMax) * 768 + k0 + ch * 8;
        else if (tile == 1) src = Al + (size_t)min(aRow0 + row, aMax) * 768 + k0 + ch * 8;
        else if (tile == 2) src = Bh + (size_t)(bRow0 + row) * 768 + k0 + ch * 8;
        else                src = Bl + (size_t)(bRow0 + row) * 768 + k0 + ch * 8;
        const uint32_t dst = sbase + buf * BUF_B + tile * TILE_B + row * 80 + ch * 16;
        CPA(dst, src);
    }
    CPA_COMMIT();
}

// ---- compute one BK=32 stage (3 products into acc) -------------------------
__device__ __forceinline__ void compute_stage(
    uint32_t sbase, int buf, int lane, int wid, float acc[4][4][4])
{
    const int wm = (wid >> 2) * 64;
    const int wn = (wid & 3) * 32;
    const uint32_t b0 = sbase + buf * BUF_B;
#pragma unroll
    for (int kk = 0; kk < 2; kk++) {
        uint32_t ah[4][4], al[4][4], bh[2][4], bl[2][4];
        const int ak = kk * 16 + ((lane >> 4) << 3);
        const int arow = wm + (lane & 15);
#pragma unroll
        for (int mi = 0; mi < 4; mi++) {
            const uint32_t off = (uint32_t)((arow + mi * 16) * 80 + ak * 2);
            ldsm4(ah[mi], b0 + off);               // Ah tile
            ldsm4(al[mi], b0 + TILE_B + off);      // Al tile
        }
        const int bk = kk * 16 + (((lane >> 3) & 1) << 3);
        const int brow = wn + ((lane >> 4) << 3) + (lane & 7);
#pragma unroll
        for (int ni = 0; ni < 2; ni++) {
            const uint32_t off = (uint32_t)((brow + ni * 16) * 80 + bk * 2);
            ldsm4(bh[ni], b0 + 2 * TILE_B + off);  // Bh
            ldsm4(bl[ni], b0 + 3 * TILE_B + off);  // Bl
        }
#pragma unroll
        for (int mi = 0; mi < 4; mi++)
#pragma unroll
            for (int nj = 0; nj < 4; nj++) {
                const int ni = nj >> 1, rs = (nj & 1) * 2;
                uint32_t bH[2] = {bh[ni][rs], bh[ni][rs + 1]};
                uint32_t bL[2] = {bl[ni][rs], bl[ni][rs + 1]};
                mma_bf16(acc[mi][nj], ah[mi], bH);
                mma_bf16(acc[mi][nj], ah[mi], bL);
                mma_bf16(acc[mi][nj], al[mi], bH);
            }
    }
}

__device__ __forceinline__ void mma_mainloop(
    const bf16* Ah, const bf16* Al, const bf16* Bh, const bf16* Bl,
    int aRow0, int aMax, int bRow0, char* smem, float acc[4][4][4],
    int tid, int lane, int wid)
{
    const uint32_t sbase = smem_u32(smem);
    issue_stage(Ah, Al, Bh, Bl, aRow0, aMax, bRow0, sbase, 0, 0, tid);
#pragma unroll 1
    for (int s = 0; s < 24; s++) {
        CPA_WAIT0();
        __syncthreads();
        if (s < 23)
            issue_stage(Ah, Al, Bh, Bl, aRow0, aMax, bRow0, sbase,
                        (s + 1) * 32, (s + 1) & 1, tid);
        compute_stage(sbase, s & 1, lane, wid, acc);
    }
}

// ============================================================================
// input conversion: fp32 -> bf16 hi/lo (tokens + entity_cls)
// ============================================================================
__device__ __forceinline__ void split4(const float4 v, uint2& h, uint2& l) {
    unsigned short hb[4], lb[4];
    const float vv[4] = {v.x, v.y, v.z, v.w};
#pragma unroll
    for (int e = 0; e < 4; e++) {
        bf16 hh = __float2bfloat16(vv[e]);
        bf16 ll = __float2bfloat16(vv[e] - __bfloat162float(hh));
        hb[e] = *(unsigned short*)&hh;
        lb[e] = *(unsigned short*)&ll;
    }
    h.x = (uint32_t)hb[0] | ((uint32_t)hb[1] << 16);
    h.y = (uint32_t)hb[2] | ((uint32_t)hb[3] << 16);
    l.x = (uint32_t)lb[0] | ((uint32_t)lb[1] << 16);
    l.y = (uint32_t)lb[2] | ((uint32_t)lb[3] << 16);
}

__global__ void split_inputs_kernel(const float* __restrict__ et,
                                    const float* __restrict__ mt,
                                    const float* __restrict__ ec)
{
    const float* src; bf16 *hp, *lp; int n;
    switch (blockIdx.z) {
        case 0: src = et; hp = g_eth; lp = g_etl; n = MQ * DIN;  break;
        case 1: src = mt; hp = g_mth; lp = g_mtl; n = MKV * DIN; break;
        default: src = ec; hp = g_ech; lp = g_ecl; n = NA * DIN; break;
    }
    const int idx = (blockIdx.x * 256 + threadIdx.x) * 4;
    if (idx >= n) return;
    uint2 h, l;
    split4(*(const float4*)&src[idx], h, l);
    *(uint2*)&hp[idx] = h;
    *(uint2*)&lp[idx] = l;
}

// W [768][768] row-major -> W^T [n][k] bf16 hi/lo
__global__ void __launch_bounds__(256) wtrans_kernel(
    const float* __restrict__ Wq, const float* __restrict__ Wk,
    const float* __restrict__ Wv, const float* __restrict__ Wc)
{
    __shared__ float s[64][65];
    const float* W; bf16 *hp, *lp;
    switch (blockIdx.z) {
        case 0: W = Wq; hp = g_wqh; lp = g_wql; break;
        case 1: W = Wk; hp = g_wkh; lp = g_wkl; break;
        case 2: W = Wv; hp = g_wvh; lp = g_wvl; break;
        default: W = Wc; hp = g_wch; lp = g_wcl; break;
    }
    const int k0 = blockIdx.y * 64, n0 = blockIdx.x * 64;
    const int tid = threadIdx.x;
#pragma unroll
    for (int p = 0; p < 16; p++) {
        const int row = p * 4 + (tid >> 6), col = tid & 63;
        s[row][col] = W[(size_t)(k0 + row) * HD + n0 + col];
    }
    __syncthreads();
#pragma unroll
    for (int p = 0; p < 4; p++) {
        const int c = tid + p * 256;
        const int orow = c >> 4, oc = (c & 15) * 4;   // output n-row, k-col
        float4 v = make_float4(s[oc][orow], s[oc + 1][orow], s[oc + 2][orow], s[oc + 3][orow]);
        uint2 h, l;
        split4(v, h, l);
        const size_t o = (size_t)(n0 + orow) * HD + k0 + oc;
        *(uint2*)&hp[o] = h;
        *(uint2*)&lp[o] = l;
    }
}

// ============================================================================
// projections via mma.sync: C = A @ W + bias (NT against W^T), fp32 out
// grid (6, 41): y<8 q | y<24 k | y<40 v | y==40 ecls
// ============================================================================
__global__ void __launch_bounds__(256) proj_mma_kernel(
    const float* __restrict__ bq, const float* __restrict__ bk,
    const float* __restrict__ bv, const float* __restrict__ bc)
{
    extern __shared__ char smem[];
    const bf16 *Ah, *Al, *Bh, *Bl; const float* bias; float* C; int m0, M;
    const int y = blockIdx.y;
    if (y < 8)       { Ah = g_eth; Al = g_etl; Bh = g_wqh; Bl = g_wql; bias = bq; C = g_q;    m0 = y * 128;        M = MQ;  }
    else if (y < 24) { Ah = g_mth; Al = g_mtl; Bh = g_wkh; Bl = g_wkl; bias = bk; C = g_k;    m0 = (y - 8) * 128;  M = MKV; }
    else if (y < 40) { Ah = g_mth; Al = g_mtl; Bh = g_wvh; Bl = g_wvl; bias = bv; C = g_v;    m0 = (y - 24) * 128; M = MKV; }
    else             { Ah = g_ech; Al = g_ecl; Bh = g_wch; Bl = g_wcl; bias = bc; C = g_ecls; m0 = 0;              M = NA;  }
    const int n0 = blockIdx.x * 128;
    const int tid = threadIdx.x, lane = tid & 31, wid = tid >> 5;

    float acc[4][4][4] = {};
    mma_mainloop(Ah, Al, Bh, Bl, m0, M - 1, n0, smem, acc, tid, lane, wid);

    const int wm = (wid >> 2) * 64, wn = (wid & 3) * 32;
#pragma unroll
    for (int mi = 0; mi < 4; mi++) {
        const int r0 = m0 + wm + mi * 16 + (lane >> 2);
#pragma unroll
        for (int nj = 0; nj < 4; nj++) {
            const int col = n0 + wn + nj * 8 + (lane & 3) * 2;
            const float b0 = bias[col], b1 = bias[col + 1];
            if (r0 < M)
                *(float2*)&C[(size_t)r0 * HD + col] =
                    make_float2(acc[mi][nj][0] + b0, acc[mi][nj][1] + b1);
            if (r0 + 8 < M)
                *(float2*)&C[(size_t)(r0 + 8) * HD + col] =
                    make_float2(acc[mi][nj][2] + b0, acc[mi][nj][3] + b1);
        }
    }
}

// ============================================================================
// NT cosine GEMM via mma.sync: T = exp( (q@k^T) * qinv * kinv * 10 )
// ============================================================================
__global__ void __launch_bounds__(256) ntexp_mma_kernel(float* __restrict__ C)
{
    extern __shared__ char smem[];
    const int m0 = blockIdx.y * 128, n0 = blockIdx.x * 128;
    const int tid = threadIdx.x, lane = tid & 31, wid = tid >> 5;

    float acc[4][4][4] = {};
    mma_mainloop(g_qh, g_ql, g_kh, g_kl, m0, MQ - 1, n0, smem, acc, tid, lane, wid);

    const int wm = (wid >> 2) * 64, wn = (wid & 3) * 32;
#pragma unroll
    for (int mi = 0; mi < 4; mi++) {
        const int r0 = m0 + wm + mi * 16 + (lane >> 2);
        const float ai0 = g_qinv[r0] * OT_INV_EPS;
        const float ai1 = g_qinv[r0 + 8] * OT_INV_EPS;
#pragma unroll
        for (int nj = 0; nj < 4; nj++) {
            const int col = n0 + wn + nj * 8 + (lane & 3) * 2;
            const float b0 = g_kinv[col], b1 = g_kinv[col + 1];
            *(float2*)&C[(size_t)r0 * MKV + col] =
                make_float2(__expf(acc[mi][nj][0] * ai0 * b0),
                            __expf(acc[mi][nj][1] * ai0 * b1));
            *(float2*)&C[(size_t)(r0 + 8) * MKV + col] =
                make_float2(__expf(acc[mi][nj][2] * ai1 * b0),
                            __expf(acc[mi][nj][3] * ai1 * b1));
        }
    }
}

// ============================================================================
// row L2-norm inverse + fp32 -> bf16 hi/lo split conversion (q and k)
// ============================================================================
__global__ void rownorm_convert_kernel()
{
    int row = blockIdx.x * 8 + (threadIdx.x >> 5);
    int lane = threadIdx.x & 31;
    const float* x; float* inv; bf16 *hp, *lp;
    if (row < MQ) {
        x = g_q + (size_t)row * HD; inv = g_qinv + row;
        hp = g_qh + (size_t)row * HD; lp = g_ql + (size_t)row * HD;
    } else {
        int r2 = row - MQ;
        x = g_k + (size_t)r2 * HD; inv = g_kinv + r2;
        hp = g_kh + (size_t)r2 * HD; lp = g_kl + (size_t)r2 * HD;
    }
    float s = 0.f;
#pragma unroll
    for (int p = 0; p < 6; p++) {
        const int d = lane * 4 + p * 128;
        float4 v4 = *(const float4*)&x[d];
        s += v4.x * v4.x + v4.y * v4.y + v4.z * v4.z + v4.w * v4.w;
        uint2 h, l;
        split4(v4, h, l);
        *(uint2*)&hp[d] = h;
        *(uint2*)&lp[d] = l;
    }
    s = warp_sum(s);
    if (lane == 0) *inv = 1.0f / fmaxf(sqrtf(s), 1e-8f);
}

// ============================================================================
// Sinkhorn (u/v vector form): warp per 32x32 tile
// ============================================================================
__global__ void __launch_bounds__(256) sinkhorn_kernel(
    const float* __restrict__ Tin, float* __restrict__ Tp)
{
    __shared__ float st[8][32 * 36];
    const int wl = threadIdx.x >> 5, lane = threadIdx.x & 31;
    const int tile = blockIdx.x * 8 + wl;
    const int a = tile >> 6, b = tile & 63;

    const float* src = Tin + (size_t)(a * 32 + lane) * MKV + b * 32;
    float Q[32];
#pragma unroll
    for (int p = 0; p < 8; p++) {
        float4 v4 = *(const float4*)&src[p * 4];
        Q[p * 4 + 0] = v4.x; Q[p * 4 + 1] = v4.y;
        Q[p * 4 + 2] = v4.z; Q[p * 4 + 3] = v4.w;
    }
    float* S = st[wl];
#pragma unroll
    for (int p = 0; p < 8; p++)
        *(float4*)&S[lane * 36 + p * 4] =
            make_float4(Q[p * 4], Q[p * 4 + 1], Q[p * 4 + 2], Q[p * 4 + 3]);
    __syncwarp();
    float QT[32];
#pragma unroll
    for (int j = 0; j < 32; j++) QT[j] = S[j * 36 + lane];

    float v_all[32];
#pragma unroll
    for (int j = 0; j < 32; j++) v_all[j] = 1.0f;

#pragma unroll 1
    for (int it = 0; it < 10; it++) {
        float s = 0.f;
#pragma unroll
        for (int j = 0; j < 32; j++) s = fmaf(Q[j], v_all[j], s);
        const float u = __fdividef(1.0f, s);
#pragma unroll
        for (int j = 0; j < 32; j++) v_all[j] = __shfl_sync(0xffffffffu, u, j);
        float s2 = 0.f;
#pragma unroll
        for (int j = 0; j < 32; j++) s2 = fmaf(QT[j], v_all[j], s2);
        const float v = __fdividef(1.0f, s2);
#pragma unroll
        for (int j = 0; j < 32; j++) v_all[j] = __shfl_sync(0xffffffffu, v, j);
    }

    float n2 = 0.f;
#pragma unroll
    for (int j = 0; j < 32; j++) {
        Q[j] *= v_all[j];
        n2 = fmaf(Q[j], Q[j], n2);
    }
    const float sc = __fdividef(1.0f, fmaxf(sqrtf(n2), 1e-12f));
    float* dst = Tp + (size_t)tile * 1024 + lane * 32;
#pragma unroll
    for (int p = 0; p < 8; p++)
        *(float4*)&dst[p * 4] = make_float4(Q[p * 4] * sc, Q[p * 4 + 1] * sc,
                                            Q[p * 4 + 2] * sc, Q[p * 4 + 3] * sc);
}

// ============================================================================
// fused attend + LN1 + softpool + LN2 + scores (validated round 3)
// ============================================================================
__global__ void __launch_bounds__(256, 2) attend_kernel(
    const float* __restrict__ Tp, const float* __restrict__ q,
    const float* __restrict__ v, const float* __restrict__ ecls,
    const float* __restrict__ entity_cls, const float* __restrict__ mention_cls,
    const float* __restrict__ ln1_g, const float* __restrict__ ln1_b,
    const float* __restrict__ Wsp, const float* __restrict__ bsp,
    const float* __restrict__ ln2_g, const float* __restrict__ ln2_b,
    float* __restrict__ out)
{
    extern __shared__ float sm[];
    float* satt  = sm;             // 24576
    float* sTt   = satt + 24576;   // 1152
    float* sWsp  = sTt + 1152;     // 768
    float* spool = sWsp + 768;     // 768
    float* sS    = spool + 768;    // 32
    float* sW    = sS + 32;        // 32
    float* sred  = sW + 32;        // 64

    const int a = blockIdx.y, b = blockIdx.x;
    const int tid = threadIdx.x, lane = tid & 31, wid = tid >> 5;

    const float* Tb = Tp + (size_t)(a * 64 + b) * 1024;
    for (int t = tid; t < 1024; t += 256) {
        int i = t >> 5, j = t & 31;
        sTt[j * 36 + i] = Tb[t];
    }
    for (int t = tid; t < 768; t += 256) sWsp[t] = Wsp[t];
    __syncthreads();

    {
        const int i0 = (wid & 3) * 8;
        const int dbase0 = (wid >> 2) * 384 + lane * 4;
        const float* qa = q + (size_t)(a * 32) * HD;
        const float* vb = v + (size_t)b * 32 * HD;
#pragma unroll 1
        for (int c = 0; c < 3; c++) {
            const int d = dbase0 + c * 128;
            u64 acc[8][2];
#pragma unroll
            for (int ii = 0; ii < 8; ii++) {
                ulonglong2 qv = *(const ulonglong2*)&qa[(i0 + ii) * HD + d];
                acc[ii][0] = qv.x; acc[ii][1] = qv.y;
            }
#pragma unroll 8
            for (int j = 0; j < 32; j++) {
                const ulonglong2 vv = *(const ulonglong2*)&vb[(size_t)j * HD + d];
                float4 t0 = *(const float4*)&sTt[j * 36 + i0];
                float4 t1 = *(const float4*)&sTt[j * 36 + i0 + 4];
                u64 td[8] = {dup2(t0.x), dup2(t0.y), dup2(t0.z), dup2(t0.w),
                             dup2(t1.x), dup2(t1.y), dup2(t1.z), dup2(t1.w)};
#pragma unroll
                for (int ii = 0; ii < 8; ii++) {
                    fma2(acc[ii][0], td[ii], vv.x);
                    fma2(acc[ii][1], td[ii], vv.y);
                }
            }
#pragma unroll
            for (int ii = 0; ii < 8; ii++) {
                ulonglong2 o; o.x = acc[ii][0]; o.y = acc[ii][1];
                *(ulonglong2*)&satt[(i0 + ii) * HD + d] = o;
            }
        }
    }
    __syncthreads();

    const float bsp0 = bsp[0];
#pragma unroll 1
    for (int rr = 0; rr < 4; rr++) {
        const int i = wid + rr * 8;
        float* row = &satt[i * HD];
        float s = 0.f, sq = 0.f;
#pragma unroll
        for (int p = 0; p < 6; p++) {
            float4 x = *(float4*)&row[lane * 4 + p * 128];
            s += x.x + x.y + x.z + x.w;
            sq += x.x * x.x + x.y * x.y + x.z * x.z + x.w * x.w;
        }
        s = warp_sum(s); sq = warp_sum(sq);
        const float mean = s * (1.0f / HD);
        const float var = sq * (1.0f / HD) - mean * mean;
        const float rstd = rsqrtf(var + 1e-5f);
        float sc = 0.f;
#pragma unroll
        for (int p = 0; p < 6; p++) {
            const int d = lane * 4 + p * 128;
            float4 x  = *(float4*)&row[d];
            float4 g  = *(const float4*)&ln1_g[d];
            float4 bb = *(const float4*)&ln1_b[d];
            float4 w4 = *(const float4*)&sWsp[d];
            float4 y;
            y.x = (x.x - mean) * rstd * g.x + bb.x;
            y.y = (x.y - mean) * rstd * g.y + bb.y;
            y.z = (x.z - mean) * rstd * g.z + bb.z;
            y.w = (x.w - mean) * rstd * g.w + bb.w;
            *(float4*)&row[d] = y;
            sc += y.x * w4.x + y.y * w4.y + y.z * w4.z + y.w * w4.w;
        }
        sc = warp_sum(sc);
        if (lane == 0) sS[i] = sc + bsp0;
    }
    __syncthreads();

    if (wid == 0) {
        float sval = sS[lane];
        float mx = warp_max(sval);
        float e = expf(sval - mx);
        float sum = warp_sum(e);
        sW[lane] = e / sum;
    }
    __syncthreads();

    for (int d = tid; d < HD; d += 256) {
        float p = 0.f;
#pragma unroll
        for (int i = 0; i < 32; i++) p = fmaf(sW[i], satt[i * HD + d], p);
        spool[d] = p;
    }
    __syncthreads();

    float s = 0.f, sq = 0.f;
    for (int d = tid; d < HD; d += 256) {
        float x = spool[d];
        s += x; sq += x * x;
    }
    s = warp_sum(s); sq = warp_sum(sq);
    if (lane == 0) { sred[wid] = s; sred[8 + wid] = sq; }
    __syncthreads();
    if (tid == 0) {
        float ts = 0.f, tq = 0.f;
#pragma unroll
        for (int w = 0; w < 8; w++) { ts += sred[w]; tq += sred[8 + w]; }
        sred[16] = ts; sred[17] = tq;
    }
    __syncthreads();
    const float mean2 = sred[16] * (1.0f / HD);
    const float var2 = sred[17] * (1.0f / HD) - mean2 * mean2;
    const float rstd2 = rsqrtf(var2 + 1e-5f);

    const float* ea  = ecls + (size_t)a * HD;
    const float* eca = entity_cls + (size_t)a * HD;
    const float* mcb = mention_cls + (size_t)b * HD;
    float g2l = 0.f, g2g = 0.f;
    for (int d = tid; d < HD; d += 256) {
        float ctx = (spool[d] - mean2) * rstd2 * ln2_g[d] + ln2_b[d];
        g2l = fmaf(ea[d], ctx, g2l);
        g2g = fmaf(eca[d], mcb[d], g2g);
    }
    g2l = warp_sum(g2l); g2g = warp_sum(g2g);
    __syncthreads();
    if (lane == 0) { sred[wid] = g2l; sred[8 + wid] = g2g; }
    __syncthreads();
    if (tid == 0) {
        float tl = 0.f, tg = 0.f;
#pragma unroll
        for (int w = 0; w < 8; w++) { tl += sred[w]; tg += sred[8 + w]; }
        out[b * NA + a] = 0.5f * (tl + tg);
    }
}

// ---------------------------------------------------------------------------
extern "C" void kernel_launch(void* const* d_in, const int* in_sizes, int n_in,
                              void* d_out, int out_size)
{
    const float* entity_cls     = (const float*)d_in[0];
    const float* entity_tokens  = (const float*)d_in[1];
    const float* mention_cls    = (const float*)d_in[2];
    const float* mention_tokens = (const float*)d_in[3];
    const float* Wq   = (const float*)d_in[4];
    const float* bq   = (const float*)d_in[5];
    const float* Wk   = (const float*)d_in[6];
    const float* bk   = (const float*)d_in[7];
    const float* Wv   = (const float*)d_in[8];
    const float* bv   = (const float*)d_in[9];
    const float* ln1g = (const float*)d_in[10];
    const float* ln1b = (const float*)d_in[11];
    const float* Wcls = (const float*)d_in[12];
    const float* bcls = (const float*)d_in[13];
    const float* Wsp  = (const float*)d_in[14];
    const float* bsp  = (const float*)d_in[15];
    const float* ln2g = (const float*)d_in[16];
    const float* ln2b = (const float*)d_in[17];
    float* out = (float*)d_out;

    float *pq, *pv, *pecls, *pT, *pTp;
    cudaGetSymbolAddress((void**)&pq,    g_q);
    cudaGetSymbolAddress((void**)&pv,    g_v);
    cudaGetSymbolAddress((void**)&pecls, g_ecls);
    cudaGetSymbolAddress((void**)&pT,    g_T);
    cudaGetSymbolAddress((void**)&pTp,   g_Tp);

    // 1. input conversions (tokens/ecls split; W transpose+split)
    split_inputs_kernel<<<dim3(1536, 1, 3), 256>>>(entity_tokens, mention_tokens, entity_cls);
    wtrans_kernel<<<dim3(12, 12, 4), 256>>>(Wq, Wk, Wv, Wcls);

    // 2. projections on tensor cores
    cudaFuncSetAttribute(proj_mma_kernel, cudaFuncAttributeMaxDynamicSharedMemorySize, SMEM_MMA);
    proj_mma_kernel<<<dim3(6, 41), 256, SMEM_MMA>>>(bq, bk, bv, bcls);

    // 3. inverse row norms + bf16 hi/lo of q,k
    rownorm_convert_kernel<<<(MQ + MKV) / 8, 256>>>();

    // 4. cosine-sim GEMM fused with exp(C/eps), tensor cores
    cudaFuncSetAttribute(ntexp_mma_kernel, cudaFuncAttributeMaxDynamicSharedMemorySize, SMEM_MMA);
    ntexp_mma_kernel<<<dim3(16, 8), 256, SMEM_MMA>>>(pT);

    // 5. Sinkhorn (u/v form) + final L2 row normalize; packed output
    sinkhorn_kernel<<<256, 256>>>(pT, pTp);

    // 6. fused attend / LN1 / softpool / LN2 / scores / g2g
    const int smem_bytes = (24576 + 1152 + 768 + 768 + 32 + 32 + 64) * 4;
    cudaFuncSetAttribute(attend_kernel, cudaFuncAttributeMaxDynamicSharedMemorySize, smem_bytes);
    attend_kernel<<<dim3(BB, NA), 256, smem_bytes>>>(
        pTp, pq, pv, pecls, entity_cls, mention_cls,
        ln1g, ln1b, Wsp, bsp, ln2g, ln2b, out);
}